// round 4
// baseline (speedup 1.0000x reference)
#include <cuda_runtime.h>

#define NN 50000
#define EE 800000
#define FF 602
#define HH 32
#define CC 41
#define BN_EPS 1e-5f
#define FULLMASK 0xffffffffu
#define NB_SCAN ((NN + 255) / 256)   // 196

#define FF_PAD 608                    // Ws rows padded (zero-filled) for k-loop overrun
#define GR 64                         // rows per gemm1 block

// ---------------- scratch (device globals) ----------------------------------
static __device__ float d_y  [NN * HH];
static __device__ float d_h1 [NN * HH];
static __device__ float d_h2 [NN * HH];
static __device__ float d_stats[4 * HH];
static __device__ int   d_counts[NN];
static __device__ int   d_rowptr[NN];
static __device__ int   d_cursor[NN];
static __device__ int   d_colsorted[EE];
static __device__ int   d_bsum[256];

// ---------------- K1: y[N,32] = x[N,602] @ W1a[602,32] — no shuffles --------
// Thread = (1 row, 8 cols). Per k: 1 LDS(x, pad-33 conflict-free) +
// 2 LDS.128 (W row, 8-thread broadcast) + 8 FFMA.  FFMA-pipe bound.
__global__ void __launch_bounds__(256) k_gemm1(const float* __restrict__ x,
                                               const float* __restrict__ W1a) {
    extern __shared__ float sm[];
    float* Ws = sm;                    // FF_PAD * HH
    float* xs = sm + FF_PAD * HH;      // GR * 33

    for (int i = threadIdx.x; i < FF * HH; i += 256) Ws[i] = W1a[i];
    for (int i = FF * HH + threadIdx.x; i < FF_PAD * HH; i += 256) Ws[i] = 0.f;

    const int r_loc = threadIdx.x >> 2;        // 0..63
    const int cg    = (threadIdx.x & 3) * 8;   // 0,8,16,24
    const int row   = blockIdx.x * GR + r_loc;

    float acc[8];
#pragma unroll
    for (int j = 0; j < 8; j++) acc[j] = 0.f;

    for (int kb = 0; kb < FF; kb += 32) {
        const int kw = (FF - kb < 32) ? (FF - kb) : 32;
        __syncthreads();
        // stage x tile: 64 rows x 32 k (zero-pad OOB)
        for (int i = threadIdx.x; i < GR * 32; i += 256) {
            int r = i >> 5, k = i & 31;
            int grow = blockIdx.x * GR + r;
            xs[r * 33 + k] = (k < kw && grow < NN)
                           ? x[(size_t)grow * FF + kb + k] : 0.f;
        }
        __syncthreads();
#pragma unroll 8
        for (int k = 0; k < 32; k++) {
            float xv = xs[r_loc * 33 + k];
            const float* wrow = &Ws[(kb + k) * HH + cg];
            float4 w0 = *(const float4*)(wrow);
            float4 w1 = *(const float4*)(wrow + 4);
            acc[0] += xv * w0.x; acc[1] += xv * w0.y;
            acc[2] += xv * w0.z; acc[3] += xv * w0.w;
            acc[4] += xv * w1.x; acc[5] += xv * w1.y;
            acc[6] += xv * w1.z; acc[7] += xv * w1.w;
        }
    }
    if (row < NN) {
        float4 o0 = make_float4(acc[0], acc[1], acc[2], acc[3]);
        float4 o1 = make_float4(acc[4], acc[5], acc[6], acc[7]);
        *(float4*)&d_y[(size_t)row * HH + cg]     = o0;
        *(float4*)&d_y[(size_t)row * HH + cg + 4] = o1;
    }
}

// ---------------- CSR build --------------------------------------------------
__global__ void k_hist(const int* __restrict__ row) {
    int t = blockIdx.x * 256 + threadIdx.x;
    int base = t * 4;
    if (base >= EE) return;
    int4 r4 = *(const int4*)(row + base);
    atomicAdd(&d_counts[r4.x], 1);
    atomicAdd(&d_counts[r4.y], 1);
    atomicAdd(&d_counts[r4.z], 1);
    atomicAdd(&d_counts[r4.w], 1);
}

__global__ void k_scan1() {
    if (blockIdx.x == 0 && threadIdx.x < 4 * HH) d_stats[threadIdx.x] = 0.f;
    __shared__ int sh[256];
    int i = blockIdx.x * 256 + threadIdx.x;
    int v = (i < NN) ? d_counts[i] : 0;
    sh[threadIdx.x] = v;
    __syncthreads();
    for (int off = 128; off > 0; off >>= 1) {
        if (threadIdx.x < off) sh[threadIdx.x] += sh[threadIdx.x + off];
        __syncthreads();
    }
    if (threadIdx.x == 0) d_bsum[blockIdx.x] = sh[0];
}

__global__ void k_scan3() {
    __shared__ int shb[256];
    __shared__ int sh[256];
    int tid = threadIdx.x;

    int bv = (tid < NB_SCAN) ? d_bsum[tid] : 0;
    shb[tid] = bv;
    __syncthreads();
    for (int off = 1; off < 256; off <<= 1) {
        int t = (tid >= off) ? shb[tid - off] : 0;
        __syncthreads();
        shb[tid] += t;
        __syncthreads();
    }
    int blk = blockIdx.x;
    int boff = shb[blk] - d_bsum[blk];
    __syncthreads();

    int i = blk * 256 + tid;
    int c = (i < NN) ? d_counts[i] : 0;
    sh[tid] = c;
    __syncthreads();
    for (int off = 1; off < 256; off <<= 1) {
        int t = (tid >= off) ? sh[tid - off] : 0;
        __syncthreads();
        sh[tid] += t;
        __syncthreads();
    }
    int start = boff + sh[tid] - c;
    if (i < NN) { d_rowptr[i] = start; d_cursor[i] = start; }
}

__global__ void k_scatter(const int* __restrict__ row, const int* __restrict__ col) {
    int t = blockIdx.x * 256 + threadIdx.x;
    int base = t * 4;
    if (base >= EE) return;
    int4 r4 = *(const int4*)(row + base);
    int4 c4 = *(const int4*)(col + base);
    int p0 = atomicAdd(&d_cursor[r4.x], 1);
    int p1 = atomicAdd(&d_cursor[r4.y], 1);
    int p2 = atomicAdd(&d_cursor[r4.z], 1);
    int p3 = atomicAdd(&d_cursor[r4.w], 1);
    d_colsorted[p0] = c4.x;
    d_colsorted[p1] = c4.y;
    d_colsorted[p2] = c4.z;
    d_colsorted[p3] = c4.w;
}

// ---------------- gather (idx broadcast via shfl — only deg/4 shfls) --------
__device__ __forceinline__ float gather_raw(const float* __restrict__ src,
                                            int s0, int deg, int lane) {
    float acc = 0.f;
    for (int e0 = 0; e0 < deg; e0 += 32) {
        int rem = deg - e0;
        if (rem > 32) rem = 32;
        int idx = (lane < rem) ? d_colsorted[s0 + e0 + lane] : 0;
        int j = 0;
        for (; j + 4 <= rem; j += 4) {
            int c0 = __shfl_sync(FULLMASK, idx, j);
            int c1 = __shfl_sync(FULLMASK, idx, j + 1);
            int c2 = __shfl_sync(FULLMASK, idx, j + 2);
            int c3 = __shfl_sync(FULLMASK, idx, j + 3);
            acc += src[(size_t)c0 * HH + lane];
            acc += src[(size_t)c1 * HH + lane];
            acc += src[(size_t)c2 * HH + lane];
            acc += src[(size_t)c3 * HH + lane];
        }
        for (; j < rem; j++) {
            int c = __shfl_sync(FULLMASK, idx, j);
            acc += src[(size_t)c * HH + lane];
        }
    }
    return acc;
}

// smem-staged 32x32 matvec: o[lane] = o + sum_j z[j] * WT[lane][j]
__device__ __forceinline__ float matvec32(const float* __restrict__ zrow,
                                          const float* __restrict__ wrow,
                                          float o) {
#pragma unroll
    for (int j4 = 0; j4 < 32; j4 += 4) {
        float4 zv = *(const float4*)(zrow + j4);   // broadcast
        float4 wv = *(const float4*)(wrow + j4);
        o += zv.x * wv.x + zv.y * wv.y + zv.z * wv.z + zv.w * wv.w;
    }
    return o;
}

// conv1: h1 = relu(y[n] + agg(y) + b1a) @ W1b + b1b ; stats1
__global__ void __launch_bounds__(1024) k_gin1(
    const float* __restrict__ ba, const float* __restrict__ Wb,
    const float* __restrict__ bb) {
    __shared__ float WbT[HH][36];
    __shared__ float zs [32][36];
    __shared__ float red1[32][32];
    __shared__ float red2[32][32];
    {
        int i = threadIdx.x;                 // 1024 = 32*32
        int j = i >> 5, c = i & 31;
        WbT[c][j] = Wb[j * HH + c];
    }
    __syncthreads();

    const int lane = threadIdx.x & 31;
    const int warp = threadIdx.x >> 5;
    const int n = blockIdx.x * 32 + warp;

    float s = 0.f, sq = 0.f;
    if (n < NN) {
        int s0  = d_rowptr[n];
        int deg = d_counts[n];
        float acc = gather_raw(d_y, s0, deg, lane);
        float z = d_y[(size_t)n * HH + lane] + acc + ba[lane];
        z = fmaxf(z, 0.f);
        zs[warp][lane] = z;
        __syncwarp();
        float o = matvec32(zs[warp], WbT[lane], bb[lane]);
        d_h1[(size_t)n * HH + lane] = o;
        s = o; sq = o * o;
    }
    red1[warp][lane] = s;
    red2[warp][lane] = sq;
    __syncthreads();
    if (warp == 0) {
        float t1 = 0.f, t2 = 0.f;
#pragma unroll
        for (int w = 0; w < 32; w++) { t1 += red1[w][lane]; t2 += red2[w][lane]; }
        atomicAdd(&d_stats[lane],      t1);
        atomicAdd(&d_stats[HH + lane], t2);
    }
}

// conv2: BN1 folded; h2 = relu((g+agg)@W2a+b2a)@W2b+b2b ; stats2
__global__ void __launch_bounds__(1024) k_gin2(
    const float* __restrict__ g1, const float* __restrict__ be1,
    const float* __restrict__ Wa, const float* __restrict__ ba,
    const float* __restrict__ Wb, const float* __restrict__ bb) {
    __shared__ float WaT[HH][36];
    __shared__ float WbT[HH][36];
    __shared__ float zs [32][36];
    __shared__ float red1[32][32];
    __shared__ float red2[32][32];
    {
        int i = threadIdx.x;
        int j = i >> 5, c = i & 31;
        WaT[c][j] = Wa[j * HH + c];
        WbT[c][j] = Wb[j * HH + c];
    }
    __syncthreads();

    const int lane = threadIdx.x & 31;
    const int warp = threadIdx.x >> 5;
    const int n = blockIdx.x * 32 + warp;

    float m = d_stats[lane] * (1.f / NN);
    float v = d_stats[HH + lane] * (1.f / NN) - m * m;
    float scale = g1[lane] * rsqrtf(v + BN_EPS);
    float shift = be1[lane] - m * scale;

    float s = 0.f, sq = 0.f;
    if (n < NN) {
        int s0  = d_rowptr[n];
        int deg = d_counts[n];
        float raw = gather_raw(d_h1, s0, deg, lane);
        raw += d_h1[(size_t)n * HH + lane];
        float t = raw * scale + (float)(deg + 1) * shift;
        zs[warp][lane] = t;
        __syncwarp();
        float u = matvec32(zs[warp], WaT[lane], ba[lane]);
        u = fmaxf(u, 0.f);
        __syncwarp();
        zs[warp][lane] = u;
        __syncwarp();
        float o = matvec32(zs[warp], WbT[lane], bb[lane]);
        d_h2[(size_t)n * HH + lane] = o;
        s = o; sq = o * o;
    }
    red1[warp][lane] = s;
    red2[warp][lane] = sq;
    __syncthreads();
    if (warp == 0) {
        float t1 = 0.f, t2 = 0.f;
#pragma unroll
        for (int w = 0; w < 32; w++) { t1 += red1[w][lane]; t2 += red2[w][lane]; }
        atomicAdd(&d_stats[2 * HH + lane], t1);
        atomicAdd(&d_stats[3 * HH + lane], t2);
    }
}

// ---------------- head -------------------------------------------------------
__global__ void __launch_bounds__(256) k_head(
    const float* __restrict__ Wf1, const float* __restrict__ bf1,
    const float* __restrict__ Wf2, const float* __restrict__ bf2,
    const float* __restrict__ g2, const float* __restrict__ be2,
    float* __restrict__ outp) {
    __shared__ float W1T[HH][36];
    __shared__ float W2T[48][36];     // 41 used, padded
    __shared__ float zs [8][36];
    for (int i = threadIdx.x; i < HH * HH; i += 256) {
        int j = i >> 5, c = i & 31;
        W1T[c][j] = Wf1[j * HH + c];
    }
    for (int i = threadIdx.x; i < HH * CC; i += 256) {
        int j = i / CC, c = i % CC;
        W2T[c][j] = Wf2[j * CC + c];
    }
    __syncthreads();

    const int lane = threadIdx.x & 31;
    const int warp = threadIdx.x >> 5;
    const int gw   = blockIdx.x * 8 + warp;
    const int nw   = gridDim.x * 8;

    float m = d_stats[2 * HH + lane] * (1.f / NN);
    float v = d_stats[3 * HH + lane] * (1.f / NN) - m * m;
    float scale = g2[lane] * rsqrtf(v + BN_EPS);
    float shift = be2[lane] - m * scale;

    const float bf1L = bf1[lane];
    const float b0 = bf2[lane];
    const float b1 = (lane < CC - HH) ? bf2[lane + HH] : 0.f;

    for (int r = gw; r < NN; r += nw) {
        float gv = d_h2[(size_t)r * HH + lane] * scale + shift;
        zs[warp][lane] = gv;
        __syncwarp();
        float z = matvec32(zs[warp], W1T[lane], bf1L);
        z = fmaxf(z, 0.f);
        __syncwarp();
        zs[warp][lane] = z;
        __syncwarp();
        float a0 = matvec32(zs[warp], W2T[lane], b0);
        float a1 = b1;
        if (lane < CC - HH)
            a1 = matvec32(zs[warp], W2T[lane + HH], b1);
        outp[(size_t)r * CC + lane] = a0;
        if (lane < CC - HH) outp[(size_t)r * CC + lane + HH] = a1;
        __syncwarp();
    }
}

// ---------------- launcher ----------------------------------------------------
extern "C" void kernel_launch(void* const* d_in, const int* in_sizes, int n_in,
                              void* d_out, int out_size) {
    const float* x   = (const float*)d_in[0];
    const int*   row = (const int*)  d_in[1];
    const int*   col = (const int*)  d_in[2];
    const float* W1a = (const float*)d_in[3];
    const float* b1a = (const float*)d_in[4];
    const float* W1b = (const float*)d_in[5];
    const float* b1b = (const float*)d_in[6];
    const float* g1  = (const float*)d_in[7];
    const float* be1 = (const float*)d_in[8];
    const float* W2a = (const float*)d_in[9];
    const float* b2a = (const float*)d_in[10];
    const float* W2b = (const float*)d_in[11];
    const float* b2b = (const float*)d_in[12];
    const float* g2  = (const float*)d_in[13];
    const float* be2 = (const float*)d_in[14];
    const float* Wf1 = (const float*)d_in[15];
    const float* bf1 = (const float*)d_in[16];
    const float* Wf2 = (const float*)d_in[17];
    const float* bf2 = (const float*)d_in[18];
    float* out = (float*)d_out;

    static cudaStream_t sA = nullptr;
    static cudaEvent_t  evFork = nullptr, evJoin = nullptr;
    static bool inited = false;
    const int gemm1_smem = (FF_PAD * HH + GR * 33) * (int)sizeof(float);
    if (!inited) {
        cudaStreamCreateWithFlags(&sA, cudaStreamNonBlocking);
        cudaEventCreateWithFlags(&evFork, cudaEventDisableTiming);
        cudaEventCreateWithFlags(&evJoin, cudaEventDisableTiming);
        cudaFuncSetAttribute(k_gemm1, cudaFuncAttributeMaxDynamicSharedMemorySize,
                             gemm1_smem);
        inited = true;
    }

    int* counts;
    cudaGetSymbolAddress((void**)&counts, d_counts);

    // fork: gemm1 on sA, CSR build on main stream
    cudaEventRecord(evFork, 0);
    cudaStreamWaitEvent(sA, evFork, 0);

    k_gemm1<<<(NN + GR - 1) / GR, 256, gemm1_smem, sA>>>(x, W1a);

    cudaMemsetAsync(counts, 0, sizeof(int) * NN, 0);
    const int eblk4 = (EE / 4 + 255) / 256;
    k_hist   <<<eblk4, 256, 0, 0>>>(row);
    k_scan1  <<<NB_SCAN, 256, 0, 0>>>();
    k_scan3  <<<NB_SCAN, 256, 0, 0>>>();
    k_scatter<<<eblk4, 256, 0, 0>>>(row, col);

    // join
    cudaEventRecord(evJoin, sA);
    cudaStreamWaitEvent(0, evJoin, 0);

    const int nblk = (NN + 31) / 32;
    k_gin1<<<nblk, 1024, 0, 0>>>(b1a, W1b, b1b);
    k_gin2<<<nblk, 1024, 0, 0>>>(g1, be1, W2a, b2a, W2b, b2b);
    k_head<<<592, 256, 0, 0>>>(Wf1, bf1, Wf2, bf2, g2, be2, out);
}

// round 5
// speedup vs baseline: 1.6506x; 1.6506x over previous
#include <cuda_runtime.h>

#define NN 50000
#define EE 800000
#define FF 602
#define HH 32
#define CC 41
#define BN_EPS 1e-5f
#define FULLMASK 0xffffffffu
#define NB_SCAN ((NN + 255) / 256)   // 196

#define KC 16                         // k-chunk for gemm1
#define GTILE 128                     // rows per gemm1 block
#define XS_STRIDE 132                 // 128 + pad(4) — float4-aligned, low conflict

// ---------------- scratch (device globals) ----------------------------------
static __device__ float d_y  [NN * HH];
static __device__ float d_h1 [NN * HH];
static __device__ float d_h2 [NN * HH];
static __device__ float d_stats[4 * HH];
static __device__ int   d_counts[NN];
static __device__ int   d_rowptr[NN];
static __device__ int   d_cursor[NN];
static __device__ int   d_colsorted[EE];
static __device__ int   d_bsum[256];

// ---------------- K1: y = x @ W1a — register-tiled 4x4 ----------------------
// Thread = 4 rows x 4 cols. Per k: 2x LDS.128 -> 16 FFMA (FFMA-pipe bound).
__global__ void __launch_bounds__(256) k_gemm1(const float* __restrict__ x,
                                               const float* __restrict__ W1a) {
    __shared__ float xs[KC][XS_STRIDE];   // transposed x tile: [k][row]
    __shared__ float Ws[KC][HH];          // W chunk: [k][col]

    const int tid = threadIdx.x;
    const int rg  = tid >> 3;             // 0..31  -> rows rg*4..rg*4+3
    const int cg  = (tid & 7) * 4;        // 0,4,...,28
    const int rowbase = blockIdx.x * GTILE;

    float acc[4][4];
#pragma unroll
    for (int i = 0; i < 4; i++)
#pragma unroll
        for (int j = 0; j < 4; j++) acc[i][j] = 0.f;

    const int kl = tid & 15;              // k lane for staging
    const int rl = tid >> 4;              // 0..15 row offset for staging

    for (int kb = 0; kb < FF; kb += KC) {
        __syncthreads();
        // stage W chunk 16x32
        for (int i = tid; i < KC * HH; i += 256) {
            int k = i >> 5, c = i & 31, kk = kb + k;
            Ws[k][c] = (kk < FF) ? W1a[kk * HH + c] : 0.f;
        }
        // stage x chunk transposed: coalesced along k
        {
            const bool kok = (kb + kl) < FF;
#pragma unroll
            for (int p = 0; p < GTILE / 16; p++) {
                int r = p * 16 + rl;
                int grow = rowbase + r;
                xs[kl][r] = (kok && grow < NN)
                          ? x[(size_t)grow * FF + kb + kl] : 0.f;
            }
        }
        __syncthreads();
#pragma unroll
        for (int k = 0; k < KC; k++) {
            float4 xv = *(const float4*)&xs[k][rg * 4];
            float4 wv = *(const float4*)&Ws[k][cg];
            acc[0][0] += xv.x * wv.x; acc[0][1] += xv.x * wv.y;
            acc[0][2] += xv.x * wv.z; acc[0][3] += xv.x * wv.w;
            acc[1][0] += xv.y * wv.x; acc[1][1] += xv.y * wv.y;
            acc[1][2] += xv.y * wv.z; acc[1][3] += xv.y * wv.w;
            acc[2][0] += xv.z * wv.x; acc[2][1] += xv.z * wv.y;
            acc[2][2] += xv.z * wv.z; acc[2][3] += xv.z * wv.w;
            acc[3][0] += xv.w * wv.x; acc[3][1] += xv.w * wv.y;
            acc[3][2] += xv.w * wv.z; acc[3][3] += xv.w * wv.w;
        }
    }
#pragma unroll
    for (int i = 0; i < 4; i++) {
        int row = rowbase + rg * 4 + i;
        if (row < NN)
            *(float4*)&d_y[(size_t)row * HH + cg] =
                make_float4(acc[i][0], acc[i][1], acc[i][2], acc[i][3]);
    }
}

// ---------------- CSR build --------------------------------------------------
__global__ void k_hist(const int* __restrict__ row) {
    int t = blockIdx.x * 256 + threadIdx.x;
    int base = t * 4;
    if (base >= EE) return;
    int4 r4 = *(const int4*)(row + base);
    atomicAdd(&d_counts[r4.x], 1);
    atomicAdd(&d_counts[r4.y], 1);
    atomicAdd(&d_counts[r4.z], 1);
    atomicAdd(&d_counts[r4.w], 1);
}

__global__ void k_scan1() {
    if (blockIdx.x == 0 && threadIdx.x < 4 * HH) d_stats[threadIdx.x] = 0.f;
    __shared__ int sh[256];
    int i = blockIdx.x * 256 + threadIdx.x;
    int v = (i < NN) ? d_counts[i] : 0;
    sh[threadIdx.x] = v;
    __syncthreads();
    for (int off = 128; off > 0; off >>= 1) {
        if (threadIdx.x < off) sh[threadIdx.x] += sh[threadIdx.x + off];
        __syncthreads();
    }
    if (threadIdx.x == 0) d_bsum[blockIdx.x] = sh[0];
}

__global__ void k_scan3() {
    __shared__ int shb[256];
    __shared__ int sh[256];
    int tid = threadIdx.x;

    int bv = (tid < NB_SCAN) ? d_bsum[tid] : 0;
    shb[tid] = bv;
    __syncthreads();
    for (int off = 1; off < 256; off <<= 1) {
        int t = (tid >= off) ? shb[tid - off] : 0;
        __syncthreads();
        shb[tid] += t;
        __syncthreads();
    }
    int blk = blockIdx.x;
    int boff = shb[blk] - d_bsum[blk];
    __syncthreads();

    int i = blk * 256 + tid;
    int c = (i < NN) ? d_counts[i] : 0;
    sh[tid] = c;
    __syncthreads();
    for (int off = 1; off < 256; off <<= 1) {
        int t = (tid >= off) ? sh[tid - off] : 0;
        __syncthreads();
        sh[tid] += t;
        __syncthreads();
    }
    int start = boff + sh[tid] - c;
    if (i < NN) { d_rowptr[i] = start; d_cursor[i] = start; }
}

__global__ void k_scatter(const int* __restrict__ row, const int* __restrict__ col) {
    int t = blockIdx.x * 256 + threadIdx.x;
    int base = t * 4;
    if (base >= EE) return;
    int4 r4 = *(const int4*)(row + base);
    int4 c4 = *(const int4*)(col + base);
    int p0 = atomicAdd(&d_cursor[r4.x], 1);
    int p1 = atomicAdd(&d_cursor[r4.y], 1);
    int p2 = atomicAdd(&d_cursor[r4.z], 1);
    int p3 = atomicAdd(&d_cursor[r4.w], 1);
    d_colsorted[p0] = c4.x;
    d_colsorted[p1] = c4.y;
    d_colsorted[p2] = c4.z;
    d_colsorted[p3] = c4.w;
}

// ---------------- gather -----------------------------------------------------
__device__ __forceinline__ float gather_raw(const float* __restrict__ src,
                                            int s0, int deg, int lane) {
    float acc = 0.f;
    for (int e0 = 0; e0 < deg; e0 += 32) {
        int rem = deg - e0;
        if (rem > 32) rem = 32;
        int idx = (lane < rem) ? d_colsorted[s0 + e0 + lane] : 0;
        int j = 0;
        for (; j + 4 <= rem; j += 4) {
            int c0 = __shfl_sync(FULLMASK, idx, j);
            int c1 = __shfl_sync(FULLMASK, idx, j + 1);
            int c2 = __shfl_sync(FULLMASK, idx, j + 2);
            int c3 = __shfl_sync(FULLMASK, idx, j + 3);
            acc += src[(size_t)c0 * HH + lane];
            acc += src[(size_t)c1 * HH + lane];
            acc += src[(size_t)c2 * HH + lane];
            acc += src[(size_t)c3 * HH + lane];
        }
        for (; j < rem; j++) {
            int c = __shfl_sync(FULLMASK, idx, j);
            acc += src[(size_t)c * HH + lane];
        }
    }
    return acc;
}

// conv1: h1 = relu(y[n] + agg(y) + b1a) @ W1b + b1b ; stats1  (round-3 form)
__global__ void __launch_bounds__(1024) k_gin1(
    const float* __restrict__ ba, const float* __restrict__ Wb,
    const float* __restrict__ bb) {
    __shared__ float Wsb[HH * HH];
    __shared__ float red1[32][32];
    __shared__ float red2[32][32];
    for (int i = threadIdx.x; i < HH * HH; i += 1024) Wsb[i] = Wb[i];
    __syncthreads();

    const int lane = threadIdx.x & 31;
    const int warp = threadIdx.x >> 5;
    const int n = blockIdx.x * 32 + warp;

    float s = 0.f, sq = 0.f;
    if (n < NN) {
        int s0  = d_rowptr[n];
        int deg = d_counts[n];
        float acc = gather_raw(d_y, s0, deg, lane);
        float z = d_y[(size_t)n * HH + lane] + acc + ba[lane];
        z = fmaxf(z, 0.f);
        float o = bb[lane];
#pragma unroll
        for (int j = 0; j < HH; j++)
            o += __shfl_sync(FULLMASK, z, j) * Wsb[j * HH + lane];
        d_h1[(size_t)n * HH + lane] = o;
        s = o; sq = o * o;
    }
    red1[warp][lane] = s;
    red2[warp][lane] = sq;
    __syncthreads();
    if (warp == 0) {
        float t1 = 0.f, t2 = 0.f;
#pragma unroll
        for (int w = 0; w < 32; w++) { t1 += red1[w][lane]; t2 += red2[w][lane]; }
        atomicAdd(&d_stats[lane],      t1);
        atomicAdd(&d_stats[HH + lane], t2);
    }
}

// conv2: BN1 folded; h2 = relu((g+agg)@W2a+b2a)@W2b+b2b ; stats2 (round-3 form)
__global__ void __launch_bounds__(1024) k_gin2(
    const float* __restrict__ g1, const float* __restrict__ be1,
    const float* __restrict__ Wa, const float* __restrict__ ba,
    const float* __restrict__ Wb, const float* __restrict__ bb) {
    __shared__ float Wsa[HH * HH];
    __shared__ float Wsb[HH * HH];
    __shared__ float red1[32][32];
    __shared__ float red2[32][32];
    for (int i = threadIdx.x; i < HH * HH; i += 1024) { Wsa[i] = Wa[i]; Wsb[i] = Wb[i]; }
    __syncthreads();

    const int lane = threadIdx.x & 31;
    const int warp = threadIdx.x >> 5;
    const int n = blockIdx.x * 32 + warp;

    float m = d_stats[lane] * (1.f / NN);
    float v = d_stats[HH + lane] * (1.f / NN) - m * m;
    float scale = g1[lane] * rsqrtf(v + BN_EPS);
    float shift = be1[lane] - m * scale;

    float s = 0.f, sq = 0.f;
    if (n < NN) {
        int s0  = d_rowptr[n];
        int deg = d_counts[n];
        float raw = gather_raw(d_h1, s0, deg, lane);
        raw += d_h1[(size_t)n * HH + lane];
        float t = raw * scale + (float)(deg + 1) * shift;
        float u = ba[lane];
#pragma unroll
        for (int j = 0; j < HH; j++)
            u += __shfl_sync(FULLMASK, t, j) * Wsa[j * HH + lane];
        u = fmaxf(u, 0.f);
        float o = bb[lane];
#pragma unroll
        for (int j = 0; j < HH; j++)
            o += __shfl_sync(FULLMASK, u, j) * Wsb[j * HH + lane];
        d_h2[(size_t)n * HH + lane] = o;
        s = o; sq = o * o;
    }
    red1[warp][lane] = s;
    red2[warp][lane] = sq;
    __syncthreads();
    if (warp == 0) {
        float t1 = 0.f, t2 = 0.f;
#pragma unroll
        for (int w = 0; w < 32; w++) { t1 += red1[w][lane]; t2 += red2[w][lane]; }
        atomicAdd(&d_stats[2 * HH + lane], t1);
        atomicAdd(&d_stats[3 * HH + lane], t2);
    }
}

// ---------------- head (round-3 form) ----------------------------------------
__global__ void k_head(const float* __restrict__ Wf1, const float* __restrict__ bf1,
                       const float* __restrict__ Wf2, const float* __restrict__ bf2,
                       const float* __restrict__ g2, const float* __restrict__ be2,
                       float* __restrict__ outp) {
    __shared__ float Ws1[HH * HH];
    __shared__ float Ws2[HH * CC];
    for (int i = threadIdx.x; i < HH * HH; i += blockDim.x) Ws1[i] = Wf1[i];
    for (int i = threadIdx.x; i < HH * CC; i += blockDim.x) Ws2[i] = Wf2[i];
    __syncthreads();

    const int lane = threadIdx.x & 31;
    const int gw   = (blockIdx.x * blockDim.x + threadIdx.x) >> 5;
    const int nw   = (gridDim.x * blockDim.x) >> 5;

    float m = d_stats[2 * HH + lane] * (1.f / NN);
    float v = d_stats[3 * HH + lane] * (1.f / NN) - m * m;
    float scale = g2[lane] * rsqrtf(v + BN_EPS);
    float shift = be2[lane] - m * scale;

    const float bf1L = bf1[lane];
    const float b0 = bf2[lane];
    const float b1 = (lane < CC - HH) ? bf2[lane + HH] : 0.f;

    for (int r = gw; r < NN; r += nw) {
        float gv = d_h2[(size_t)r * HH + lane] * scale + shift;
        float z = bf1L;
#pragma unroll
        for (int j = 0; j < HH; j++)
            z += __shfl_sync(FULLMASK, gv, j) * Ws1[j * HH + lane];
        z = fmaxf(z, 0.f);

        float a0 = b0, a1 = b1;
#pragma unroll
        for (int j = 0; j < HH; j++) {
            float zj = __shfl_sync(FULLMASK, z, j);
            a0 += zj * Ws2[j * CC + lane];
            if (lane < CC - HH) a1 += zj * Ws2[j * CC + lane + HH];
        }
        outp[(size_t)r * CC + lane] = a0;
        if (lane < CC - HH) outp[(size_t)r * CC + lane + HH] = a1;
    }
}

// ---------------- launcher ----------------------------------------------------
extern "C" void kernel_launch(void* const* d_in, const int* in_sizes, int n_in,
                              void* d_out, int out_size) {
    const float* x   = (const float*)d_in[0];
    const int*   row = (const int*)  d_in[1];
    const int*   col = (const int*)  d_in[2];
    const float* W1a = (const float*)d_in[3];
    const float* b1a = (const float*)d_in[4];
    const float* W1b = (const float*)d_in[5];
    const float* b1b = (const float*)d_in[6];
    const float* g1  = (const float*)d_in[7];
    const float* be1 = (const float*)d_in[8];
    const float* W2a = (const float*)d_in[9];
    const float* b2a = (const float*)d_in[10];
    const float* W2b = (const float*)d_in[11];
    const float* b2b = (const float*)d_in[12];
    const float* g2  = (const float*)d_in[13];
    const float* be2 = (const float*)d_in[14];
    const float* Wf1 = (const float*)d_in[15];
    const float* bf1 = (const float*)d_in[16];
    const float* Wf2 = (const float*)d_in[17];
    const float* bf2 = (const float*)d_in[18];
    float* out = (float*)d_out;

    static cudaStream_t sA = nullptr;
    static cudaEvent_t  evFork = nullptr, evJoin = nullptr;
    static bool inited = false;
    if (!inited) {
        cudaStreamCreateWithFlags(&sA, cudaStreamNonBlocking);
        cudaEventCreateWithFlags(&evFork, cudaEventDisableTiming);
        cudaEventCreateWithFlags(&evJoin, cudaEventDisableTiming);
        inited = true;
    }

    int* counts;
    cudaGetSymbolAddress((void**)&counts, d_counts);

    // fork: gemm1 on sA, CSR build on main stream
    cudaEventRecord(evFork, 0);
    cudaStreamWaitEvent(sA, evFork, 0);

    k_gemm1<<<(NN + GTILE - 1) / GTILE, 256, 0, sA>>>(x, W1a);

    cudaMemsetAsync(counts, 0, sizeof(int) * NN, 0);
    const int eblk4 = (EE / 4 + 255) / 256;
    k_hist   <<<eblk4, 256, 0, 0>>>(row);
    k_scan1  <<<NB_SCAN, 256, 0, 0>>>();
    k_scan3  <<<NB_SCAN, 256, 0, 0>>>();
    k_scatter<<<eblk4, 256, 0, 0>>>(row, col);

    // join
    cudaEventRecord(evJoin, sA);
    cudaStreamWaitEvent(0, evJoin, 0);

    const int nblk = (NN + 31) / 32;
    k_gin1<<<nblk, 1024, 0, 0>>>(b1a, W1b, b1b);
    k_gin2<<<nblk, 1024, 0, 0>>>(g1, be1, W2a, b2a, W2b, b2b);
    k_head<<<592, 256, 0, 0>>>(Wf1, bf1, Wf2, bf2, g2, be2, out);
}